// round 3
// baseline (speedup 1.0000x reference)
#include <cuda_runtime.h>
#include <math.h>

// Problem constants (fixed by setup_inputs)
#define Bc 128          // batch
#define Nc 96           // num deltas
#define Dc 3072         // C*H*W
#define Kc 10           // classes
#define RPW 4           // rows (n-values) per warp, same b
#define WARPS 16
#define THREADS (WARPS*32)
#define NGROUPS (Bc * (Nc / RPW))        // 3072 warp-groups
#define BLOCKS1 (NGROUPS / WARPS)        // 192
#define SMEM_BYTES (Kc * Dc * 4)         // 122880 B

__device__ float g_l1[Bc * Nc];
__device__ float g_l2[Bc * Nc];
__device__ float g_part[Bc];

__global__ __launch_bounds__(THREADS, 1)
void logits_kernel(const float* __restrict__ imgs,
                   const float* __restrict__ deltas,
                   const float* __restrict__ Wm,
                   const float* __restrict__ bias,
                   const int*   __restrict__ labels)
{
    extern __shared__ float sW[];   // [Kc][Dc], transposed from W[d][k]

    // Cooperative load+transpose of W (coalesced global reads)
    for (int idx = threadIdx.x; idx < Dc * Kc; idx += THREADS) {
        int d = idx / Kc, k = idx % Kc;
        sW[k * Dc + d] = Wm[idx];
    }
    __syncthreads();

    const int warp = threadIdx.x >> 5;
    const int lane = threadIdx.x & 31;
    const int g    = blockIdx.x * WARPS + warp;   // 0..3071
    const int b    = g % Bc;
    const int n0   = (g / Bc) * RPW;

    const float4* img4 = (const float4*)(imgs + (size_t)b * Dc);
    const float4* dp[RPW];
#pragma unroll
    for (int r = 0; r < RPW; r++)
        dp[r] = (const float4*)(deltas + ((size_t)(n0 + r) * Bc + b) * Dc);

    float acc[RPW][Kc];
#pragma unroll
    for (int r = 0; r < RPW; r++)
#pragma unroll
        for (int k = 0; k < Kc; k++) acc[r][k] = 0.0f;

#pragma unroll 2
    for (int i = 0; i < Dc / 128; i++) {
        const int e = i * 32 + lane;       // float4 index within row
        float4 xi = __ldg(img4 + e);

        float4 w[Kc];
#pragma unroll
        for (int k = 0; k < Kc; k++)
            w[k] = *(const float4*)(sW + k * Dc + e * 4);

#pragma unroll
        for (int r = 0; r < RPW; r++) {
            float4 xd = __ldg(dp[r] + e);
            float x0 = fminf(fmaxf(xi.x + xd.x, 0.0f), 1.0f);
            float x1 = fminf(fmaxf(xi.y + xd.y, 0.0f), 1.0f);
            float x2 = fminf(fmaxf(xi.z + xd.z, 0.0f), 1.0f);
            float x3 = fminf(fmaxf(xi.w + xd.w, 0.0f), 1.0f);
#pragma unroll
            for (int k = 0; k < Kc; k++) {
                acc[r][k] += x0 * w[k].x;
                acc[r][k] += x1 * w[k].y;
                acc[r][k] += x2 * w[k].z;
                acc[r][k] += x3 * w[k].w;
            }
        }
    }

    // Per-row epilogue: warp reduce 10 logits, compute loss1/loss2
#pragma unroll
    for (int r = 0; r < RPW; r++) {
        float lg[Kc];
#pragma unroll
        for (int k = 0; k < Kc; k++) {
            float v = acc[r][k];
            v += __shfl_xor_sync(0xFFFFFFFFu, v, 16);
            v += __shfl_xor_sync(0xFFFFFFFFu, v, 8);
            v += __shfl_xor_sync(0xFFFFFFFFu, v, 4);
            v += __shfl_xor_sync(0xFFFFFFFFu, v, 2);
            v += __shfl_xor_sync(0xFFFFFFFFu, v, 1);
            lg[k] = v;
        }
        if (lane == 0) {
#pragma unroll
            for (int k = 0; k < Kc; k++) lg[k] += __ldg(bias + k);

            // argmax (first occurrence, matches top_k tie rule)
            float m = lg[0]; int t1 = 0;
#pragma unroll
            for (int k = 1; k < Kc; k++)
                if (lg[k] > m) { m = lg[k]; t1 = k; }

            float s = 0.0f;
#pragma unroll
            for (int k = 0; k < Kc; k++) s += expf(lg[k] - m);
            float lse = m + logf(s);

            int lab = __ldg(labels + b);
            float logit_lab = lg[0];
#pragma unroll
            for (int k = 1; k < Kc; k++)
                if (k == lab) logit_lab = lg[k];
            float loss1 = lse - logit_lab;

            // second-best (first occurrence among k != t1)
            float m2 = -INFINITY; int t2 = 0;
#pragma unroll
            for (int k = 0; k < Kc; k++)
                if (k != t1 && lg[k] > m2) { m2 = lg[k]; t2 = k; }
            float logit_t2 = lg[0];
#pragma unroll
            for (int k = 1; k < Kc; k++)
                if (k == t2) logit_t2 = lg[k];

            float loss2 = (t1 == lab) ? (lse - logit_t2) : -10000.0f;

            g_l1[b * Nc + (n0 + r)] = loss1;
            g_l2[b * Nc + (n0 + r)] = loss2;
        }
    }
}

// Per-batch-row stable rank-select (replicates stable argsort exactly)
__global__ void select_kernel(const int* __restrict__ indp)
{
    __shared__ float sd[Nc];
    __shared__ float sl1[Nc];
    __shared__ float sSel;

    const int b = blockIdx.x;
    const int j = threadIdx.x;   // 0..95

    float l1v = 0.0f, l2v = 0.0f, dv = 0.0f;
    if (j < Nc) {
        l1v = g_l1[b * Nc + j];
        l2v = g_l2[b * Nc + j];
        dv  = l1v - l2v;
        sd[j]  = dv;
        sl1[j] = l1v;
    }
    __syncthreads();

    const int ind = __ldg(indp);
    if (j < Nc) {
        int cnt = 0;
        for (int i = 0; i < Nc; i++) {
            float di = sd[i];
            cnt += (di < dv) || (di == dv && i < j);
        }
        if (cnt == ind) sSel = l2v;   // exactly one j satisfies this
    }
    __syncthreads();

    if (j == 0) {
        float s = 0.0f;
        for (int i = 0; i < Nc; i++) s += sl1[i];
        g_part[b] = s / (float)Nc - sSel;
    }
}

__global__ void reduce_kernel(float* __restrict__ out)
{
    if (threadIdx.x == 0) {
        float a = 0.0f;
#pragma unroll
        for (int i = 0; i < Bc; i++) a += g_part[i];
        out[0] = a / (float)Bc;
    }
}

extern "C" void kernel_launch(void* const* d_in, const int* in_sizes, int n_in,
                              void* d_out, int out_size)
{
    const float* imgs   = (const float*)d_in[0];
    const float* deltas = (const float*)d_in[1];
    const float* Wm     = (const float*)d_in[2];
    const float* bias   = (const float*)d_in[3];
    const int*   labels = (const int*)d_in[4];
    const int*   indp   = (const int*)d_in[5];
    float* out = (float*)d_out;

    cudaFuncSetAttribute(logits_kernel,
                         cudaFuncAttributeMaxDynamicSharedMemorySize, SMEM_BYTES);

    logits_kernel<<<BLOCKS1, THREADS, SMEM_BYTES>>>(imgs, deltas, Wm, bias, labels);
    select_kernel<<<Bc, Nc>>>(indp);
    reduce_kernel<<<1, 32>>>(out);
}